// round 5
// baseline (speedup 1.0000x reference)
#include <cuda_runtime.h>

#define BB 4096
#define TT 512
#define HH 32

typedef unsigned long long u64;

__device__ __forceinline__ u64 pk2(float lo, float hi) {
    u64 r; asm("mov.b64 %0, {%1,%2};" : "=l"(r) : "f"(lo), "f"(hi)); return r;
}
__device__ __forceinline__ void unpk2(u64 v, float& a, float& b) {
    asm("mov.b64 {%0,%1}, %2;" : "=f"(a), "=f"(b) : "l"(v));
}
// Packed f32x2 FMA / ADD (Blackwell full-rate; ptxas never auto-fuses these)
__device__ __forceinline__ u64 ffma2(u64 a, u64 b, u64 c) {
    u64 d; asm("fma.rn.f32x2 %0, %1, %2, %3;" : "=l"(d) : "l"(a), "l"(b), "l"(c));
    return d;
}
__device__ __forceinline__ u64 fadd2(u64 a, u64 b) {
    u64 d; asm("add.rn.f32x2 %0, %1, %2;" : "=l"(d) : "l"(a), "l"(b));
    return d;
}

// tanh with 2*log2(e) pre-folded into the pre-activation:
// tanh(v) = 1 - 2*rcp(ex2(v') + 1),  v' = 2*log2(e)*v
__device__ __forceinline__ float tanh_scaled(float vp) {
    float e; asm("ex2.approx.f32 %0, %1;" : "=f"(e) : "f"(vp));
    float r; asm("rcp.approx.f32 %0, %1;" : "=f"(r) : "f"(e + 1.0f));
    return fmaf(-2.0f, r, 1.0f);
}

__global__ void __launch_bounds__(32, 16)   // force <=128 regs -> 16 warps/SM
rnn2_kernel(const float* __restrict__ x,       // [B, T, 1]
            const float* __restrict__ hstate,  // [2, B, H]
            const float* __restrict__ Wih0,    // [H, 1]
            const float* __restrict__ Whh0,    // [H, H]
            const float* __restrict__ bih0, const float* __restrict__ bhh0,
            const float* __restrict__ Wih1,    // [H, H]
            const float* __restrict__ Whh1,    // [H, H]
            const float* __restrict__ bih1, const float* __restrict__ bhh1,
            const float* __restrict__ Wfc,     // [1, H]
            const float* __restrict__ bfc,     // [1]
            float* __restrict__ out)           // [B] pred ++ [2,B,H] h_new
{
    // Single-buffer h per layer: within one warp every LDS of a phase
    // precedes the STS in program order, so no double buffering is needed.
    // 128B rows; all lanes read the same 16B -> broadcast LDS.128.
    __shared__ __align__(16) float sh0[HH];
    __shared__ __align__(16) float sh1[HH];

    const int j = threadIdx.x;           // 0..31, one warp per block
    const int b = blockIdx.x;            // one batch per block

    const float SC = 2.885390081777927f; // 2*log2(e), folded into weights

    // Weight rows for output neuron j, scaled, packed as f32x2 (k, k+1).
    u64 w0[16], wi1[16], wh1[16];
    {
        const float2* p = (const float2*)(Whh0 + j * HH);
        #pragma unroll
        for (int i = 0; i < 16; i++) { float2 f = p[i]; w0[i]  = pk2(f.x*SC, f.y*SC); }
        p = (const float2*)(Wih1 + j * HH);
        #pragma unroll
        for (int i = 0; i < 16; i++) { float2 f = p[i]; wi1[i] = pk2(f.x*SC, f.y*SC); }
        p = (const float2*)(Whh1 + j * HH);
        #pragma unroll
        for (int i = 0; i < 16; i++) { float2 f = p[i]; wh1[i] = pk2(f.x*SC, f.y*SC); }
    }
    const float wx0 = Wih0[j] * SC;
    const float bb0 = (bih0[j] + bhh0[j]) * SC;
    const float bb1 = (bih1[j] + bhh1[j]) * SC;

    sh0[j] = hstate[(size_t)b * HH + j];
    sh1[j] = hstate[(size_t)BB * HH + (size_t)b * HH + j];
    __syncwarp();

    const float* xb = x + (size_t)b * TT;

    // ---- prologue: L0(0): h0'(0) = tanh(Whh0@h0 + Wih0*x0 + b) ----
    {
        u64 a  = pk2(fmaf(wx0, xb[0], bb0), 0.f);
        u64 ab = pk2(0.f, 0.f);
        const ulonglong2* hp = (const ulonglong2*)sh0;
        #pragma unroll
        for (int i = 0; i < 8; i++) {
            ulonglong2 v = hp[i];
            a  = ffma2(w0[2*i],     v.x, a);
            ab = ffma2(w0[2*i + 1], v.y, ab);
        }
        float lo, hi;
        unpk2(fadd2(a, ab), lo, hi);
        sh0[j] = tanh_scaled(lo + hi);
    }
    __syncwarp();

    float xv = xb[1];   // x for L0(1)
    float h1n = 0.f;

    // ---- pipelined mainloop: phase t_e computes L0(t_e+1) and L1(t_e) ----
    // for t_e = 0 .. TT-2   (L1(TT-1) done in epilogue)
    #pragma unroll 1
    for (int te = 0; te < TT - 1; te++) {
        const float xt = xv;
        int tn = te + 2; if (tn > TT - 1) tn = TT - 1;
        xv = xb[tn];

        // accumulators: biases folded into init
        u64 a0  = pk2(fmaf(wx0, xt, bb0), 0.f);
        u64 a0b = pk2(0.f, 0.f);
        u64 a1  = pk2(bb1, 0.f);
        u64 a1b = pk2(0.f, 0.f);

        // one LDS.128 of h0'(t_e) feeds BOTH Whh0 (L0) and Wih1 (L1)
        #pragma unroll
        for (int i = 0; i < 8; i++) {
            ulonglong2 v = ((const ulonglong2*)sh0)[i];
            a0  = ffma2(w0[2*i],      v.x, a0);
            a0b = ffma2(w0[2*i + 1],  v.y, a0b);
            a1  = ffma2(wi1[2*i],     v.x, a1);
            a1b = ffma2(wi1[2*i + 1], v.y, a1b);
        }
        // Whh1 @ h1'(t_e-1), sharing the same two accumulator chains
        #pragma unroll
        for (int i = 0; i < 8; i++) {
            ulonglong2 u = ((const ulonglong2*)sh1)[i];
            a1  = ffma2(wh1[2*i],     u.x, a1);
            a1b = ffma2(wh1[2*i + 1], u.y, a1b);
        }

        float lo, hi;
        unpk2(fadd2(a0, a0b), lo, hi);
        sh0[j] = tanh_scaled(lo + hi);          // h0'(t_e+1)

        unpk2(fadd2(a1, a1b), lo, hi);
        h1n = tanh_scaled(lo + hi);             // h1'(t_e)
        sh1[j] = h1n;
        __syncwarp();
    }

    // ---- epilogue: L1(TT-1) ----
    {
        u64 a1  = pk2(bb1, 0.f);
        u64 a1b = pk2(0.f, 0.f);
        #pragma unroll
        for (int i = 0; i < 8; i++) {
            ulonglong2 v = ((const ulonglong2*)sh0)[i];
            a1  = ffma2(wi1[2*i],     v.x, a1);
            a1b = ffma2(wi1[2*i + 1], v.y, a1b);
        }
        #pragma unroll
        for (int i = 0; i < 8; i++) {
            ulonglong2 u = ((const ulonglong2*)sh1)[i];
            a1  = ffma2(wh1[2*i],     u.x, a1);
            a1b = ffma2(wh1[2*i + 1], u.y, a1b);
        }
        float lo, hi;
        unpk2(fadd2(a1, a1b), lo, hi);
        h1n = tanh_scaled(lo + hi);             // h1'(TT-1)
    }

    // ---- outputs ----
    const size_t ob = (size_t)b * HH + j;
    out[BB + ob]                   = sh0[j];    // h_new[0] = h0'(TT-1)
    out[BB + (size_t)BB * HH + ob] = h1n;       // h_new[1] = h1'(TT-1)

    float p = Wfc[j] * h1n;
    #pragma unroll
    for (int off = 16; off; off >>= 1)
        p += __shfl_xor_sync(0xffffffffu, p, off);
    if (j == 0) out[b] = p + bfc[0];
}

extern "C" void kernel_launch(void* const* d_in, const int* in_sizes, int n_in,
                              void* d_out, int out_size) {
    const float* x     = (const float*)d_in[0];
    const float* hs    = (const float*)d_in[1];
    const float* Wih0  = (const float*)d_in[2];
    const float* Whh0  = (const float*)d_in[3];
    const float* bih0  = (const float*)d_in[4];
    const float* bhh0  = (const float*)d_in[5];
    const float* Wih1  = (const float*)d_in[6];
    const float* Whh1  = (const float*)d_in[7];
    const float* bih1  = (const float*)d_in[8];
    const float* bhh1  = (const float*)d_in[9];
    const float* Wfc   = (const float*)d_in[10];
    const float* bfc   = (const float*)d_in[11];
    float* out = (float*)d_out;

    rnn2_kernel<<<BB, 32>>>(x, hs, Wih0, Whh0, bih0, bhh0,
                            Wih1, Whh1, bih1, bhh1, Wfc, bfc, out);
}